// round 6
// baseline (speedup 1.0000x reference)
#include <cuda_runtime.h>
#include <math.h>

// EdgeDetection: gray -> gauss3x3(sigma=0.8) -> scharr x/y -> L2 mag, reflect-101.
// Separable composite filters on gray; fully float4-vectorized:
//   - LDG.128 gray stage (3 channels), scalar only for 4 halo columns
//   - LDS.128 horizontal 5-tap (3 loads -> 4 outputs)
//   - float4 register ring for vertical 5-tap
//   - STG.128 to all 3 output channel planes

#define TW 128
#define TH 32
#define GH 36            // TH + 4 halo rows
#define GSTRIDE 136      // row stride in floats (16B-aligned, cols 2..133 used)
#define NTHREADS 256
#define ROWS_PER_THREAD 4

__device__ __forceinline__ int reflect101(int v, int n) {
    v = (v < 0) ? -v : v;
    v = (v >= n) ? (2 * n - 2 - v) : v;
    return v;
}

__global__ __launch_bounds__(NTHREADS)
void edge_detect_kernel(const float* __restrict__ x, float* __restrict__ out,
                        int H, int W) {
    __shared__ float g[GH][GSTRIDE];

    const int x0 = blockIdx.x * TW;
    const int y0 = blockIdx.y * TH;
    const int b  = blockIdx.z;
    const int tid = threadIdx.x;

    // 1-D Gaussian [ga, gb, ga] for k=3 sigma=0.8
    const float e  = expf(-0.78125f);
    const float s  = 1.0f / (2.0f * e + 1.0f);
    const float ga = e * s;
    const float gb = s;
    // Smooth5 = conv([ga,gb,ga],[3,10,3]); Deriv5 = conv([ga,gb,ga],[-1,0,1])
    const float w0 = 3.0f * ga;
    const float w1 = 10.0f * ga + 3.0f * gb;
    const float w2 = 6.0f * ga + 10.0f * gb;

    const size_t plane = (size_t)H * W;
    const float* Rp = x + (size_t)b * 3 * plane;
    const float* Gp = Rp + plane;
    const float* Bp = Gp + plane;

    // ---- Stage 1a: interior gray, float4 loads. smem interior at cols [4,132) ----
    // 36 rows x 32 float4 = 1152 vector tasks
    for (int idx = tid; idx < GH * (TW / 4); idx += NTHREADS) {
        const int i  = idx >> 5;          // gray row 0..35
        const int jv = idx & 31;          // float4 index 0..31
        const int gy = reflect101(y0 + i - 2, H);
        const size_t o = (size_t)gy * W + x0 + 4 * jv;
        const float4 r4 = __ldg((const float4*)(Rp + o));
        const float4 g4 = __ldg((const float4*)(Gp + o));
        const float4 b4 = __ldg((const float4*)(Bp + o));
        float4 gr;
        gr.x = 0.299f * r4.x + 0.587f * g4.x + 0.114f * b4.x;
        gr.y = 0.299f * r4.y + 0.587f * g4.y + 0.114f * b4.y;
        gr.z = 0.299f * r4.z + 0.587f * g4.z + 0.114f * b4.z;
        gr.w = 0.299f * r4.w + 0.587f * g4.w + 0.114f * b4.w;
        *(float4*)&g[i][4 + 4 * jv] = gr;
    }
    // ---- Stage 1b: halo columns (smem cols 2,3 and 132,133), scalar ----
    if (tid < GH * 4) {
        const int i  = tid >> 2;
        const int hc = tid & 3;
        const int sj = (hc < 2) ? (2 + hc) : (130 + hc);        // 2,3,132,133
        const int gxr = (hc < 2) ? (x0 - 2 + hc) : (x0 + 126 + hc); // x0-2,x0-1,x0+128,x0+129
        const int gx = reflect101(gxr, W);
        const int gy = reflect101(y0 + i - 2, H);
        const size_t o = (size_t)gy * W + gx;
        g[i][sj] = 0.299f * __ldg(Rp + o) + 0.587f * __ldg(Gp + o) + 0.114f * __ldg(Bp + o);
    }
    __syncthreads();

    // ---- Stage 2+3: horizontal 5-tap (float4) + vertical ring + store ----
    const int c  = tid & 31;      // float4 column strip 0..31 (output cols 4c..4c+3)
    const int rg = tid >> 5;      // row group 0..7
    const int rbase = rg * ROWS_PER_THREAD;

    // Output col j taps smem cols j+2..j+6. Outputs 4c..4c+3 need cols 4c+2..4c+9.
    // Three aligned float4 LDS at smem cols 4c, 4c+4, 4c+8.
#define HROW(k, HX, HY) do {                                               \
        const float4 A = *(const float4*)&g[k][4 * c];                     \
        const float4 Bv = *(const float4*)&g[k][4 * c + 4];                \
        const float4 Cv = *(const float4*)&g[k][4 * c + 8];                \
        HX.x = ga * (Bv.z - A.z) + gb * (Bv.y - A.w);                      \
        HX.y = ga * (Bv.w - A.w) + gb * (Bv.z - Bv.x);                     \
        HX.z = ga * (Cv.x - Bv.x) + gb * (Bv.w - Bv.y);                    \
        HX.w = ga * (Cv.y - Bv.y) + gb * (Cv.x - Bv.z);                    \
        HY.x = w0 * (A.z + Bv.z) + w1 * (A.w + Bv.y) + w2 * Bv.x;          \
        HY.y = w0 * (A.w + Bv.w) + w1 * (Bv.x + Bv.z) + w2 * Bv.y;         \
        HY.z = w0 * (Bv.x + Cv.x) + w1 * (Bv.y + Bv.w) + w2 * Bv.z;        \
        HY.w = w0 * (Bv.y + Cv.y) + w1 * (Bv.z + Cv.x) + w2 * Bv.w;        \
    } while (0)

    float4 hx0, hx1, hx2, hx3, hx4;
    float4 hy0, hy1, hy2, hy3, hy4;
    HROW(rbase + 0, hx0, hy0);
    HROW(rbase + 1, hx1, hy1);
    HROW(rbase + 2, hx2, hy2);
    HROW(rbase + 3, hx3, hy3);

    float* outp = out + (size_t)b * 3 * plane + (size_t)(y0 + rbase) * W + (x0 + 4 * c);

    #pragma unroll
    for (int t = 0; t < ROWS_PER_THREAD; t++) {
        HROW(rbase + t + 4, hx4, hy4);
        float4 m;
        {
            const float sx = w0 * (hx0.x + hx4.x) + w1 * (hx1.x + hx3.x) + w2 * hx2.x;
            const float sy = ga * (hy4.x - hy0.x) + gb * (hy3.x - hy1.x);
            m.x = sqrtf(sx * sx + sy * sy);
        }
        {
            const float sx = w0 * (hx0.y + hx4.y) + w1 * (hx1.y + hx3.y) + w2 * hx2.y;
            const float sy = ga * (hy4.y - hy0.y) + gb * (hy3.y - hy1.y);
            m.y = sqrtf(sx * sx + sy * sy);
        }
        {
            const float sx = w0 * (hx0.z + hx4.z) + w1 * (hx1.z + hx3.z) + w2 * hx2.z;
            const float sy = ga * (hy4.z - hy0.z) + gb * (hy3.z - hy1.z);
            m.z = sqrtf(sx * sx + sy * sy);
        }
        {
            const float sx = w0 * (hx0.w + hx4.w) + w1 * (hx1.w + hx3.w) + w2 * hx2.w;
            const float sy = ga * (hy4.w - hy0.w) + gb * (hy3.w - hy1.w);
            m.w = sqrtf(sx * sx + sy * sy);
        }
        *(float4*)(outp)             = m;
        *(float4*)(outp + plane)     = m;
        *(float4*)(outp + 2 * plane) = m;
        outp += W;
        hx0 = hx1; hx1 = hx2; hx2 = hx3; hx3 = hx4;
        hy0 = hy1; hy1 = hy2; hy2 = hy3; hy3 = hy4;
    }
#undef HROW
}

extern "C" void kernel_launch(void* const* d_in, const int* in_sizes, int n_in,
                              void* d_out, int out_size) {
    const float* x = (const float*)d_in[0];
    float* out = (float*)d_out;
    const int B = 8, H = 1024, W = 1024;

    dim3 grid(W / TW, H / TH, B);
    edge_detect_kernel<<<grid, NTHREADS>>>(x, out, H, W);
}